// round 13
// baseline (speedup 1.0000x reference)
#include <cuda_runtime.h>
#include <cuda_fp16.h>
#include <cstdint>

// Problem constants
#define NN 50000
#define NND 50176          // NN padded to 49*1024 for uint4 deg scan
#define EE 1600000
#define K0 319999u         // floor(0.2*(E-1)) rank (ascending, 0-based)
#define K1 320000u
#define EPS 1e-16f
#define CAP 8192
#define PREP_BLOCKS 1184   // 148 SMs x 8 blocks (guaranteed by launch_bounds(256,8))

// ---------------- device scratch (static, no allocation) ----------------
__device__ unsigned g_hist16[65536];
__device__ unsigned g_binid[2];
__device__ unsigned g_cumbefore[2];
__device__ unsigned g_cand_cnt[2];
__device__ float    g_cand[2][CAP];
__device__ int      g_cidx[2][CAP];
__device__ float    g_thr;

__device__ float    g_attsums[NN];
__device__ __align__(16) unsigned g_deg[NND];
__device__ __align__(16) unsigned g_rowstart[NN + 1];
__device__ __align__(16) unsigned g_cursor[NN];

__device__ __align__(16) int2 g_edges[EE];        // (src, bitcast(w)) kept edges, dst-sorted

__device__ __align__(256) float  g_Y1[NN * 64];
__device__ __align__(256) float  g_Y2[NN * 64];
__device__ __align__(256) float  g_S [NN * 64];
__device__ __align__(256) __half g_H0[NN * 64];   // fp16 gather shadow (ping)
__device__ __align__(256) __half g_H1[NN * 64];   // fp16 gather shadow (pong)

// grid barrier state (ever-increasing generation)
__device__ unsigned g_bcount;
__device__ unsigned g_bgen;

__device__ __forceinline__ void gridbar() {
    __syncthreads();
    if (threadIdx.x == 0) {
        __threadfence();
        unsigned gen = *(volatile unsigned*)&g_bgen;
        if (atomicAdd(&g_bcount, 1u) == PREP_BLOCKS - 1) {
            g_bcount = 0;
            __threadfence();
            atomicAdd(&g_bgen, 1u);
        } else {
            while (*(volatile unsigned*)&g_bgen == gen) __nanosleep(128);
        }
    }
    __syncthreads();
}

// ---------------- launch 1: fused persistent preprocessing ----------------
__global__ void __launch_bounds__(256, 8)
k_prep(const float* __restrict__ att,
       const int* __restrict__ src,
       const int* __restrict__ dst,
       const float2* __restrict__ x) {
    const int t   = threadIdx.x;
    const int gid = blockIdx.x * 256 + t;
    const int gstride = PREP_BLOCKS * 256;
    const float4* att4 = (const float4*)att;

    __shared__ unsigned chs[64];     // chunk sums (qscan)
    __shared__ unsigned cscan[64];   // chunk inclusive scan
    __shared__ unsigned fscan[256];  // fine scan / select scans
    __shared__ unsigned cnt[256];    // select histogram
    __shared__ unsigned sc, scum, sb1, srank2, sb0;
    __shared__ float vsel[2];
    __shared__ float sthr;

    // ---- phase Z: zero ----
    for (int i = gid; i < 65536; i += gstride) g_hist16[i] = 0u;
    for (int i = gid; i < NND; i += gstride)   g_deg[i] = 0u;
    for (int i = gid; i < NN; i += gstride)    g_attsums[i] = 0.f;
    if (gid < 2) g_cand_cnt[gid] = 0u;
    gridbar();

    // ---- phase H: 16-bit histogram of att bit patterns ----
    for (int i = gid; i < EE / 4; i += gstride) {
        float4 v = att4[i];
        atomicAdd(&g_hist16[__float_as_uint(v.x) >> 16], 1u);
        atomicAdd(&g_hist16[__float_as_uint(v.y) >> 16], 1u);
        atomicAdd(&g_hist16[__float_as_uint(v.z) >> 16], 1u);
        atomicAdd(&g_hist16[__float_as_uint(v.w) >> 16], 1u);
    }
    gridbar();

    // ---- phase Q: locate bins of ranks K0,K1 (block 0 only, 256 thr) ----
    if (blockIdx.x == 0) {
        int w = t >> 5, lane = t & 31;
        // 8 warps x 8 chunks each; chunk = 1024 bins = 256 uint4
        for (int h = 0; h < 8; h++) {
            int c = w * 8 + h;
            unsigned acc = 0;
            #pragma unroll
            for (int k = 0; k < 8; k++) {
                uint4 v = __ldcg(&((const uint4*)g_hist16)[c * 256 + lane + 32 * k]);
                acc += v.x + v.y + v.z + v.w;
            }
            #pragma unroll
            for (int off = 16; off > 0; off >>= 1)
                acc += __shfl_down_sync(0xFFFFFFFFu, acc, off);
            if (lane == 0) chs[c] = acc;
        }
        __syncthreads();
        if (t < 64) cscan[t] = chs[t];
        __syncthreads();
        for (int off = 1; off < 64; off <<= 1) {
            unsigned v = (t < 64 && t >= off) ? cscan[t - off] : 0u;
            __syncthreads();
            if (t < 64) cscan[t] += v;
            __syncthreads();
        }
        for (int sel = 0; sel < 2; sel++) {
            unsigned rank = sel ? K1 : K0;
            if (t < 64 && rank < cscan[t] && rank >= cscan[t] - chs[t]) {
                sc = t; scum = cscan[t] - chs[t];
            }
            __syncthreads();
            unsigned mc = sc, mcum = scum;
            uint4 v = __ldcg(&((const uint4*)g_hist16)[mc * 256 + t]);   // 4 bins / thread
            unsigned lsum = v.x + v.y + v.z + v.w;
            fscan[t] = lsum;
            __syncthreads();
            for (int off = 1; off < 256; off <<= 1) {
                unsigned u = (t >= off) ? fscan[t - off] : 0u;
                __syncthreads();
                fscan[t] += u;
                __syncthreads();
            }
            unsigned r = rank - mcum;
            unsigned before = fscan[t] - lsum;
            if (r >= before && r < fscan[t]) {
                unsigned rr = r - before;
                unsigned b, pre;
                if (rr < v.x)                  { b = 0; pre = 0; }
                else if (rr < v.x + v.y)       { b = 1; pre = v.x; }
                else if (rr < v.x + v.y + v.z) { b = 2; pre = v.x + v.y; }
                else                           { b = 3; pre = v.x + v.y + v.z; }
                g_binid[sel] = mc * 1024 + t * 4 + b;
                g_cumbefore[sel] = mcum + before + pre;
            }
            __syncthreads();
        }
    }
    gridbar();

    // ---- phase C: collect candidates + tentative edge stats ----
    {
        unsigned b0 = *(volatile unsigned*)&g_binid[0];
        unsigned b1 = *(volatile unsigned*)&g_binid[1];
        unsigned FLOOR = b0 << 16;
        for (int i = gid; i < EE / 4; i += gstride) {
            float4 v = att4[i];
            float a[4] = {v.x, v.y, v.z, v.w};
            #pragma unroll
            for (int j = 0; j < 4; j++) {
                unsigned bits = __float_as_uint(a[j]);
                unsigned hi = bits >> 16;
                int e = 4 * i + j;
                if (bits > FLOOR) {
                    atomicAdd(&g_attsums[src[e]], a[j]);
                    atomicAdd(&g_deg[dst[e]], 1u);
                }
                if (hi == b0) {
                    unsigned p = atomicAdd(&g_cand_cnt[0], 1u);
                    if (p < CAP) { g_cand[0][p] = a[j]; g_cidx[0][p] = e; }
                } else if (hi == b1) {
                    unsigned p = atomicAdd(&g_cand_cnt[1], 1u);
                    if (p < CAP) { g_cand[1][p] = a[j]; g_cidx[1][p] = e; }
                }
            }
        }
    }
    gridbar();

    // ---- phase S: exact order stats + threshold + fixup (block 0, 256 thr) ----
    if (blockIdx.x == 0) {
        unsigned b0id = g_binid[0], b1id = g_binid[1];
        for (int sel = 0; sel < 2; sel++) {
            int bufi = (sel == 1 && b1id != b0id) ? 1 : 0;
            unsigned bin = (sel == 0) ? b0id : b1id;
            unsigned rank = ((sel == 0) ? K0 : K1) - g_cumbefore[sel];
            unsigned n = min(*(volatile unsigned*)&g_cand_cnt[bufi], (unsigned)CAP);

            cnt[t] = 0u;
            __syncthreads();
            for (int i = t; i < (int)n; i += 256)
                atomicAdd(&cnt[(__float_as_uint(__ldcg(&g_cand[bufi][i])) >> 8) & 255u], 1u);
            __syncthreads();
            unsigned c = cnt[t];
            fscan[t] = c;
            __syncthreads();
            for (int off = 1; off < 256; off <<= 1) {
                unsigned v = (t >= off) ? fscan[t - off] : 0u;
                __syncthreads();
                fscan[t] += v;
                __syncthreads();
            }
            if (rank < fscan[t] && rank >= fscan[t] - c) { sb1 = t; srank2 = rank - (fscan[t] - c); }
            __syncthreads();
            unsigned mb1 = sb1, r2 = srank2;
            __syncthreads();

            cnt[t] = 0u;
            __syncthreads();
            for (int i = t; i < (int)n; i += 256) {
                unsigned k = __float_as_uint(__ldcg(&g_cand[bufi][i]));
                if (((k >> 8) & 255u) == mb1) atomicAdd(&cnt[k & 255u], 1u);
            }
            __syncthreads();
            c = cnt[t];
            fscan[t] = c;
            __syncthreads();
            for (int off = 1; off < 256; off <<= 1) {
                unsigned v = (t >= off) ? fscan[t - off] : 0u;
                __syncthreads();
                fscan[t] += v;
                __syncthreads();
            }
            if (r2 < fscan[t] && r2 >= fscan[t] - c) sb0 = t;
            __syncthreads();

            if (t == 0) vsel[sel] = __uint_as_float((bin << 16) | (mb1 << 8) | sb0);
            __syncthreads();
        }
        if (t == 0) { sthr = vsel[0] + 0.8f * (vsel[1] - vsel[0]); g_thr = sthr; }
        __syncthreads();
        float thr = sthr;
        unsigned FLOOR = b0id << 16;
        int nbuf = (b1id != b0id) ? 2 : 1;
        for (int b = 0; b < nbuf; b++) {
            unsigned n = min(g_cand_cnt[b], (unsigned)CAP);
            for (int i = t; i < (int)n; i += 256) {
                float a = __ldcg(&g_cand[b][i]);
                unsigned bits = __float_as_uint(a);
                if (bits > FLOOR && a <= thr) {
                    int e = g_cidx[b][i];
                    atomicAdd(&g_attsums[src[e]], -a);
                    atomicAdd(&g_deg[dst[e]], 0xFFFFFFFFu);   // -1
                }
            }
        }
    }
    gridbar();

    // ---- phase D: degree -> CSR rowstart/cursor (blocks 0..48) ----
    if (blockIdx.x < 49) {
        int b = blockIdx.x;
        unsigned acc = 0;
        for (int c = 0; c < b; c++) {
            uint4 v = __ldcg(&((const uint4*)g_deg)[c * 256 + t]);
            acc += v.x + v.y + v.z + v.w;
        }
        fscan[t] = acc;
        __syncthreads();
        for (int off = 128; off > 0; off >>= 1) {
            if (t < off) fscan[t] += fscan[t + off];
            __syncthreads();
        }
        unsigned base = fscan[0];
        __syncthreads();

        uint4 v = __ldcg(&((const uint4*)g_deg)[b * 256 + t]);
        unsigned mysum = v.x + v.y + v.z + v.w;
        fscan[t] = mysum;
        __syncthreads();
        for (int off = 1; off < 256; off <<= 1) {
            unsigned u = (t >= off) ? fscan[t - off] : 0u;
            __syncthreads();
            fscan[t] += u;
            __syncthreads();
        }
        unsigned run = base + fscan[t] - mysum;
        int j = b * 1024 + t * 4;
        unsigned d[4] = {v.x, v.y, v.z, v.w};
        #pragma unroll
        for (int k = 0; k < 4; k++) {
            if (j + k < NN) {
                g_rowstart[j + k] = run;
                g_cursor[j + k]   = run;
                run += d[k];
            }
        }
        if (b == 48 && t == 255) g_rowstart[NN] = base + fscan[255];
    }
    gridbar();

    // ---- phase X: scatter kept edges + x -> fp16 shadow ----
    {
        float thr = *(volatile float*)&g_thr;
        for (int i = gid; i < EE; i += gstride) {
            float2 v = x[i];                              // i also indexes NN*32 float2
            ((__half2*)g_H0)[i] = __floats2half2_rn(v.x, v.y);
            float a = att[i];
            if (a > thr) {
                int s = src[i];
                int d = dst[i];
                float w = a / (__ldcg(&g_attsums[s]) + EPS);
                unsigned pos = atomicAdd(&g_cursor[d], 1u);
                g_edges[pos] = make_int2(s, __float_as_int(w));
            }
        }
    }
}

// ---------------- launches 2-5: fused RK4 stage --------------------------------
// MODE 1: gather H0(x);  yrow=x;  S  = k;   Y1 = x+0.5k; H1 = half(Y1)
// MODE 2: gather H1(y1); yrow=Y1; S += 2k;  Y2 = x+0.5k; H0 = half(Y2)
// MODE 3: gather H0(y2); yrow=Y2; S += 2k;  Y1 = x+k;    H1 = half(Y1)
// MODE 4: gather H1(y3); yrow=Y1; out = x + (S + k)/6
template <int MODE>
__global__ void k_stage(const float2* __restrict__ x, float2* __restrict__ out) {
    int gw   = (blockIdx.x * blockDim.x + threadIdx.x) >> 5;
    int lane = threadIdx.x & 31;
    if (gw >= NN) return;

    const __half2* __restrict__ Hin =
        (MODE == 1 || MODE == 3) ? (const __half2*)g_H0 : (const __half2*)g_H1;

    unsigned e0 = g_rowstart[gw];
    unsigned e1 = g_rowstart[gw + 1];

    float ax = 0.f, ay = 0.f, bx = 0.f, by = 0.f;
    unsigned e = e0;

    // peel to even e so int4 (2-edge) loads are aligned
    if (e < e1 && (e & 1u)) {
        int2 p = __ldg(&g_edges[e]);
        float2 y = __half22float2(__ldg(&Hin[p.x * 32 + lane]));
        float w = __int_as_float(p.y);
        ax = fmaf(w, y.x, ax); ay = fmaf(w, y.y, ay);
        e++;
    }
    // batch 8 edges: 4 int4 loads (2 edges each), then 8 independent gathers
    for (; e + 8 <= e1; e += 8) {
        int4 P[4];
        #pragma unroll
        for (int j = 0; j < 4; j++) P[j] = __ldg(&((const int4*)g_edges)[(e >> 1) + j]);
        __half2 H[8];
        #pragma unroll
        for (int j = 0; j < 4; j++) {
            H[2*j]   = __ldg(&Hin[P[j].x * 32 + lane]);
            H[2*j+1] = __ldg(&Hin[P[j].z * 32 + lane]);
        }
        #pragma unroll
        for (int j = 0; j < 4; j++) {
            float2 y0 = __half22float2(H[2*j]);
            float2 y1 = __half22float2(H[2*j+1]);
            float w0 = __int_as_float(P[j].y);
            float w1 = __int_as_float(P[j].w);
            ax = fmaf(w0, y0.x, ax); ay = fmaf(w0, y0.y, ay);
            bx = fmaf(w1, y1.x, bx); by = fmaf(w1, y1.y, by);
        }
    }
    for (; e < e1; e++) {
        int2 p = __ldg(&g_edges[e]);
        float2 y = __half22float2(__ldg(&Hin[p.x * 32 + lane]));
        float w = __int_as_float(p.y);
        ax = fmaf(w, y.x, ax); ay = fmaf(w, y.y, ay);
    }
    ax += bx; ay += by;

    int idx = gw * 32 + lane;
    const float2* Yin = (MODE == 1) ? x
                      : (MODE == 2) ? (const float2*)g_Y1
                      : (MODE == 3) ? (const float2*)g_Y2
                                    : (const float2*)g_Y1;
    float2 yr = Yin[idx];
    float kx = ax - yr.x;
    float ky = ay - yr.y;
    float2 xr = (MODE == 1) ? yr : x[idx];
    float2* S2 = (float2*)g_S;

    if (MODE == 1) {
        S2[idx] = make_float2(kx, ky);
        float nx = xr.x + 0.5f * kx, ny = xr.y + 0.5f * ky;
        ((float2*)g_Y1)[idx] = make_float2(nx, ny);
        ((__half2*)g_H1)[idx] = __floats2half2_rn(nx, ny);
    } else if (MODE == 2) {
        float2 s = S2[idx];
        S2[idx] = make_float2(s.x + 2.f * kx, s.y + 2.f * ky);
        float nx = xr.x + 0.5f * kx, ny = xr.y + 0.5f * ky;
        ((float2*)g_Y2)[idx] = make_float2(nx, ny);
        ((__half2*)g_H0)[idx] = __floats2half2_rn(nx, ny);
    } else if (MODE == 3) {
        float2 s = S2[idx];
        S2[idx] = make_float2(s.x + 2.f * kx, s.y + 2.f * ky);
        float nx = xr.x + kx, ny = xr.y + ky;
        ((float2*)g_Y1)[idx] = make_float2(nx, ny);
        ((__half2*)g_H1)[idx] = __floats2half2_rn(nx, ny);
    } else {
        float2 s = S2[idx];
        const float c = 1.f / 6.f;
        out[idx] = make_float2(xr.x + (s.x + kx) * c, xr.y + (s.y + ky) * c);
    }
}

// ---------------- launch ----------------
extern "C" void kernel_launch(void* const* d_in, const int* in_sizes, int n_in,
                              void* d_out, int out_size) {
    const float* x   = (const float*)d_in[0];   // [50000, 64]
    const float* att = (const float*)d_in[1];   // [1600000, 1]
    const int*   ei  = (const int*)d_in[2];     // [2, 1600000]
    const int* src = ei;
    const int* dst = ei + EE;
    float* out = (float*)d_out;

    const int T = 256;
    const int sb = (NN * 32 + T - 1) / T;       // 6250 (warp per row)

    k_prep<<<PREP_BLOCKS, T>>>(att, src, dst, (const float2*)x);   // 1
    k_stage<1><<<sb, T>>>((const float2*)x, (float2*)out);          // 2
    k_stage<2><<<sb, T>>>((const float2*)x, (float2*)out);          // 3
    k_stage<3><<<sb, T>>>((const float2*)x, (float2*)out);          // 4  <- profiled
    k_stage<4><<<sb, T>>>((const float2*)x, (float2*)out);          // 5
}

// round 14
// speedup vs baseline: 1.0622x; 1.0622x over previous
#include <cuda_runtime.h>
#include <cuda_fp16.h>
#include <cstdint>

// Problem constants
#define NN 50000
#define NND 50176          // NN padded to 49*1024
#define EE 1600000
#define K0 319999u         // floor(0.2*(E-1)) rank (ascending, 0-based)
#define K1 320000u
#define EPS 1e-16f
#define CAP 8192
#define HB 1024            // hist16q grid
#define CB 1024            // colledgesel grid

// ---------------- device scratch (static, no allocation) ----------------
__device__ unsigned g_hist16[65536];
__device__ unsigned g_binid[2];
__device__ unsigned g_cumbefore[2];
__device__ unsigned g_cand_cnt[2];
__device__ float    g_cand[2][CAP];
__device__ int      g_cidx[2][CAP];
__device__ float    g_thr;
__device__ unsigned g_done1, g_done2;     // last-block fan-in counters

__device__ float    g_attsums[NN];
__device__ __align__(16) unsigned g_deg[NND];
__device__ __align__(16) unsigned g_rowstart[NN + 1];
__device__ __align__(16) unsigned g_cursor[NN];

__device__ __align__(16) int2 g_edges[EE];        // (src, bitcast(w)) kept edges, dst-sorted

__device__ __align__(256) float  g_Y [NN * 64];   // fp32 row state (single buffer)
__device__ __align__(256) __half g_H0[NN * 64];   // fp16 gather shadow (ping)
__device__ __align__(256) __half g_H1[NN * 64];   // fp16 gather shadow (pong)

// ---------------- launch 1: hist16 + last-block inline qscan ----------------
// att in [0,1): positive floats, uint bit pattern order-isomorphic to value.
__global__ void k_hist16q(const float4* __restrict__ att4) {
    const int t = threadIdx.x;
    const int gid = blockIdx.x * 256 + t;
    for (int i = gid; i < EE / 4; i += HB * 256) {
        float4 v = att4[i];
        atomicAdd(&g_hist16[__float_as_uint(v.x) >> 16], 1u);
        atomicAdd(&g_hist16[__float_as_uint(v.y) >> 16], 1u);
        atomicAdd(&g_hist16[__float_as_uint(v.z) >> 16], 1u);
        atomicAdd(&g_hist16[__float_as_uint(v.w) >> 16], 1u);
    }
    // fan-in: last block to finish does the bin search
    __shared__ unsigned slast;
    __syncthreads();
    if (t == 0) {
        __threadfence();
        slast = (atomicAdd(&g_done1, 1u) == HB - 1) ? 1u : 0u;
    }
    __syncthreads();
    if (!slast) return;
    if (t == 0) g_done1 = 0u;

    // ---- qscan with 256 threads ----
    __shared__ unsigned chs[64];
    __shared__ unsigned cscan[64];
    __shared__ unsigned fscan[256];
    __shared__ unsigned sc, scum;
    int w = t >> 5, lane = t & 31;
    for (int h = 0; h < 8; h++) {               // 8 warps x 8 chunks
        int c = w * 8 + h;
        unsigned acc = 0;
        #pragma unroll
        for (int k = 0; k < 8; k++) {
            uint4 v = __ldcg(&((const uint4*)g_hist16)[c * 256 + lane + 32 * k]);
            acc += v.x + v.y + v.z + v.w;
        }
        #pragma unroll
        for (int off = 16; off > 0; off >>= 1)
            acc += __shfl_down_sync(0xFFFFFFFFu, acc, off);
        if (lane == 0) chs[c] = acc;
    }
    __syncthreads();
    if (t < 64) cscan[t] = chs[t];
    __syncthreads();
    for (int off = 1; off < 64; off <<= 1) {
        unsigned v = (t < 64 && t >= off) ? cscan[t - off] : 0u;
        __syncthreads();
        if (t < 64) cscan[t] += v;
        __syncthreads();
    }
    for (int sel = 0; sel < 2; sel++) {
        unsigned rank = sel ? K1 : K0;
        if (t < 64 && rank < cscan[t] && rank >= cscan[t] - chs[t]) {
            sc = t; scum = cscan[t] - chs[t];
        }
        __syncthreads();
        unsigned mc = sc, mcum = scum;
        uint4 v = __ldcg(&((const uint4*)g_hist16)[mc * 256 + t]);   // 4 bins / thread
        unsigned lsum = v.x + v.y + v.z + v.w;
        fscan[t] = lsum;
        __syncthreads();
        for (int off = 1; off < 256; off <<= 1) {
            unsigned u = (t >= off) ? fscan[t - off] : 0u;
            __syncthreads();
            fscan[t] += u;
            __syncthreads();
        }
        unsigned r = rank - mcum;
        unsigned before = fscan[t] - lsum;
        if (r >= before && r < fscan[t]) {
            unsigned rr = r - before;
            unsigned b, pre;
            if (rr < v.x)                  { b = 0; pre = 0; }
            else if (rr < v.x + v.y)       { b = 1; pre = v.x; }
            else if (rr < v.x + v.y + v.z) { b = 2; pre = v.x + v.y; }
            else                           { b = 3; pre = v.x + v.y + v.z; }
            g_binid[sel] = mc * 1024 + t * 4 + b;
            g_cumbefore[sel] = mcum + before + pre;
        }
        __syncthreads();
    }
}

// ---------------- launch 2: collect + tentative stats + last-block select/fixup ----
__global__ void k_colledgesel(const float4* __restrict__ att4,
                              const int* __restrict__ src,
                              const int* __restrict__ dst) {
    const int t = threadIdx.x;
    const int gid = blockIdx.x * 256 + t;
    unsigned b0 = g_binid[0], b1 = g_binid[1];
    unsigned FLOOR = b0 << 16;
    for (int i = gid; i < EE / 4; i += CB * 256) {
        float4 v = att4[i];
        float a[4] = {v.x, v.y, v.z, v.w};
        #pragma unroll
        for (int j = 0; j < 4; j++) {
            unsigned bits = __float_as_uint(a[j]);
            unsigned hi = bits >> 16;
            int e = 4 * i + j;
            if (bits > FLOOR) {
                atomicAdd(&g_attsums[src[e]], a[j]);
                atomicAdd(&g_deg[dst[e]], 1u);
            }
            if (hi == b0) {
                unsigned p = atomicAdd(&g_cand_cnt[0], 1u);
                if (p < CAP) { g_cand[0][p] = a[j]; g_cidx[0][p] = e; }
            } else if (hi == b1) {
                unsigned p = atomicAdd(&g_cand_cnt[1], 1u);
                if (p < CAP) { g_cand[1][p] = a[j]; g_cidx[1][p] = e; }
            }
        }
    }
    __shared__ unsigned slast;
    __syncthreads();
    if (t == 0) {
        __threadfence();
        slast = (atomicAdd(&g_done2, 1u) == CB - 1) ? 1u : 0u;
    }
    __syncthreads();
    if (!slast) return;
    if (t == 0) g_done2 = 0u;

    // ---- select (exact order stats via 2x 8-bit radix) + threshold + fixup ----
    __shared__ unsigned cnt[256];
    __shared__ unsigned fscan[256];
    __shared__ unsigned sb1, srank2, sb0;
    __shared__ float vsel[2];
    __shared__ float sthr;
    for (int sel = 0; sel < 2; sel++) {
        int bufi = (sel == 1 && b1 != b0) ? 1 : 0;
        unsigned bin = (sel == 0) ? b0 : b1;
        unsigned rank = ((sel == 0) ? K0 : K1) - g_cumbefore[sel];
        unsigned n = min(*(volatile unsigned*)&g_cand_cnt[bufi], (unsigned)CAP);

        cnt[t] = 0u;
        __syncthreads();
        for (int i = t; i < (int)n; i += 256)
            atomicAdd(&cnt[(__float_as_uint(__ldcg(&g_cand[bufi][i])) >> 8) & 255u], 1u);
        __syncthreads();
        unsigned c = cnt[t];
        fscan[t] = c;
        __syncthreads();
        for (int off = 1; off < 256; off <<= 1) {
            unsigned v = (t >= off) ? fscan[t - off] : 0u;
            __syncthreads();
            fscan[t] += v;
            __syncthreads();
        }
        if (rank < fscan[t] && rank >= fscan[t] - c) { sb1 = t; srank2 = rank - (fscan[t] - c); }
        __syncthreads();
        unsigned mb1 = sb1, r2 = srank2;
        __syncthreads();

        cnt[t] = 0u;
        __syncthreads();
        for (int i = t; i < (int)n; i += 256) {
            unsigned k = __float_as_uint(__ldcg(&g_cand[bufi][i]));
            if (((k >> 8) & 255u) == mb1) atomicAdd(&cnt[k & 255u], 1u);
        }
        __syncthreads();
        c = cnt[t];
        fscan[t] = c;
        __syncthreads();
        for (int off = 1; off < 256; off <<= 1) {
            unsigned v = (t >= off) ? fscan[t - off] : 0u;
            __syncthreads();
            fscan[t] += v;
            __syncthreads();
        }
        if (r2 < fscan[t] && r2 >= fscan[t] - c) sb0 = t;
        __syncthreads();
        if (t == 0) vsel[sel] = __uint_as_float((bin << 16) | (mb1 << 8) | sb0);
        __syncthreads();
    }
    if (t == 0) { sthr = vsel[0] + 0.8f * (vsel[1] - vsel[0]); g_thr = sthr; }
    __syncthreads();
    float thr = sthr;
    int nbuf = (b1 != b0) ? 2 : 1;
    for (int b = 0; b < nbuf; b++) {
        unsigned n = min(g_cand_cnt[b], (unsigned)CAP);
        for (int i = t; i < (int)n; i += 256) {
            float a = __ldcg(&g_cand[b][i]);
            unsigned bits = __float_as_uint(a);
            if (bits > FLOOR && a <= thr) {
                int e = g_cidx[b][i];
                atomicAdd(&g_attsums[src[e]], -a);
                atomicAdd(&g_deg[dst[e]], 0xFFFFFFFFu);   // -1
            }
        }
    }
}

// ---------------- launch 3: degree -> CSR rowstart/cursor (49 blocks) ----------------
__global__ void k_degcsr() {
    __shared__ unsigned fscan[256];
    int b = blockIdx.x, t = threadIdx.x;
    unsigned acc = 0;
    for (int c = 0; c < b; c++) {
        uint4 v = __ldcg(&((const uint4*)g_deg)[c * 256 + t]);
        acc += v.x + v.y + v.z + v.w;
    }
    fscan[t] = acc;
    __syncthreads();
    for (int off = 128; off > 0; off >>= 1) {
        if (t < off) fscan[t] += fscan[t + off];
        __syncthreads();
    }
    unsigned base = fscan[0];
    __syncthreads();

    uint4 v = __ldcg(&((const uint4*)g_deg)[b * 256 + t]);
    unsigned mysum = v.x + v.y + v.z + v.w;
    fscan[t] = mysum;
    __syncthreads();
    for (int off = 1; off < 256; off <<= 1) {
        unsigned u = (t >= off) ? fscan[t - off] : 0u;
        __syncthreads();
        fscan[t] += u;
        __syncthreads();
    }
    unsigned run = base + fscan[t] - mysum;
    int j = b * 1024 + t * 4;
    unsigned d[4] = {v.x, v.y, v.z, v.w};
    #pragma unroll
    for (int k = 0; k < 4; k++) {
        if (j + k < NN) {
            g_rowstart[j + k] = run;
            g_cursor[j + k]   = run;
            run += d[k];
        }
    }
    if (b == 48 && t == 255) g_rowstart[NN] = base + fscan[255];
}

// ---------------- launch 4 (profiled): scatter kept edges + x -> fp16 shadow --------
__global__ void k_scatterx(const float* __restrict__ att,
                           const int* __restrict__ src,
                           const int* __restrict__ dst,
                           const float2* __restrict__ x) {
    int i = blockIdx.x * blockDim.x + threadIdx.x;
    if (i >= EE) return;
    float2 v = x[i];                              // i also indexes NN*32 float2
    ((__half2*)g_H0)[i] = __floats2half2_rn(v.x, v.y);
    float a = att[i];
    if (a > g_thr) {
        int s = src[i];
        int d = dst[i];
        float w = a / (__ldcg(&g_attsums[s]) + EPS);
        unsigned pos = atomicAdd(&g_cursor[d], 1u);
        g_edges[pos] = make_int2(s, __float_as_int(w));
    }
}

// ---------------- launches 5-8: fused RK4 stage -----------------------------------
// Single fp32 row-state buffer g_Y; Butcher sum accumulated in `out`.
// MODE 1: gather H0(x);  y=x;  out  = k;        Y = x+0.5k; H1 = half(Y)
// MODE 2: gather H1(y1); y=Y;  out += 2k;       Y = x+0.5k; H0 = half(Y)
// MODE 3: gather H0(y2); y=Y;  out += 2k;       Y = x+k;    H1 = half(Y)
// MODE 4: gather H1(y3); y=Y;  out = x+(out+k)/6; self-clean scratch for next replay
template <int MODE>
__global__ void k_stage(const float2* __restrict__ x, float2* __restrict__ out) {
    // self-clean (MODE 4 only): zero scratch for the next graph replay
    if (MODE == 4) {
        int z = blockIdx.x * blockDim.x + threadIdx.x;
        if (z < 65536) g_hist16[z] = 0u;
        int z1 = z - 65536;
        if (z1 >= 0 && z1 < NND) g_deg[z1] = 0u;
        int z2 = z1 - NND;
        if (z2 >= 0 && z2 < NN) g_attsums[z2] = 0.f;
        if (z < 2) g_cand_cnt[z] = 0u;
    }

    int gw   = (blockIdx.x * blockDim.x + threadIdx.x) >> 5;
    int lane = threadIdx.x & 31;
    if (gw >= NN) return;

    const __half2* __restrict__ Hin =
        (MODE == 1 || MODE == 3) ? (const __half2*)g_H0 : (const __half2*)g_H1;

    unsigned e0 = g_rowstart[gw];
    unsigned e1 = g_rowstart[gw + 1];

    float ax = 0.f, ay = 0.f, bx = 0.f, by = 0.f;
    unsigned e = e0;
    for (; e + 8 <= e1; e += 8) {
        int2 E[8];
        #pragma unroll
        for (int j = 0; j < 8; j++) E[j] = __ldg(&g_edges[e + j]);
        __half2 H[8];
        #pragma unroll
        for (int j = 0; j < 8; j++) H[j] = __ldg(&Hin[E[j].x * 32 + lane]);
        #pragma unroll
        for (int j = 0; j < 8; j++) {
            float2 y = __half22float2(H[j]);
            float w = __int_as_float(E[j].y);
            if (j & 1) { bx = fmaf(w, y.x, bx); by = fmaf(w, y.y, by); }
            else       { ax = fmaf(w, y.x, ax); ay = fmaf(w, y.y, ay); }
        }
    }
    for (; e < e1; e++) {
        int2 p = __ldg(&g_edges[e]);
        float2 y = __half22float2(__ldg(&Hin[p.x * 32 + lane]));
        float w = __int_as_float(p.y);
        ax = fmaf(w, y.x, ax); ay = fmaf(w, y.y, ay);
    }
    ax += bx; ay += by;

    int idx = gw * 32 + lane;
    float2 xr = x[idx];
    float2 yr = (MODE == 1) ? xr : ((const float2*)g_Y)[idx];
    float kx = ax - yr.x;
    float ky = ay - yr.y;

    if (MODE == 1) {
        out[idx] = make_float2(kx, ky);
        float nx = xr.x + 0.5f * kx, ny = xr.y + 0.5f * ky;
        ((float2*)g_Y)[idx] = make_float2(nx, ny);
        ((__half2*)g_H1)[idx] = __floats2half2_rn(nx, ny);
    } else if (MODE == 2) {
        float2 o = out[idx];
        out[idx] = make_float2(o.x + 2.f * kx, o.y + 2.f * ky);
        float nx = xr.x + 0.5f * kx, ny = xr.y + 0.5f * ky;
        ((float2*)g_Y)[idx] = make_float2(nx, ny);
        ((__half2*)g_H0)[idx] = __floats2half2_rn(nx, ny);
    } else if (MODE == 3) {
        float2 o = out[idx];
        out[idx] = make_float2(o.x + 2.f * kx, o.y + 2.f * ky);
        float nx = xr.x + kx, ny = xr.y + ky;
        ((float2*)g_Y)[idx] = make_float2(nx, ny);
        ((__half2*)g_H1)[idx] = __floats2half2_rn(nx, ny);
    } else {
        float2 o = out[idx];
        const float c = 1.f / 6.f;
        out[idx] = make_float2(xr.x + (o.x + kx) * c, xr.y + (o.y + ky) * c);
    }
}

// ---------------- launch ----------------
extern "C" void kernel_launch(void* const* d_in, const int* in_sizes, int n_in,
                              void* d_out, int out_size) {
    const float* x   = (const float*)d_in[0];   // [50000, 64]
    const float* att = (const float*)d_in[1];   // [1600000, 1]
    const int*   ei  = (const int*)d_in[2];     // [2, 1600000]
    const int* src = ei;
    const int* dst = ei + EE;
    float* out = (float*)d_out;

    const int T = 256;
    const int eb = (EE + T - 1) / T;            // 6250
    const int sb = (NN * 32 + T - 1) / T;       // 6250 (warp per row)

    k_hist16q   <<<HB, T>>>((const float4*)att);                    // 1
    k_colledgesel<<<CB, T>>>((const float4*)att, src, dst);         // 2
    k_degcsr    <<<49, T>>>();                                      // 3
    k_scatterx  <<<eb, T>>>(att, src, dst, (const float2*)x);       // 4 <- profiled
    k_stage<1>  <<<sb, T>>>((const float2*)x, (float2*)out);        // 5
    k_stage<2>  <<<sb, T>>>((const float2*)x, (float2*)out);        // 6
    k_stage<3>  <<<sb, T>>>((const float2*)x, (float2*)out);        // 7
    k_stage<4>  <<<sb, T>>>((const float2*)x, (float2*)out);        // 8
}